// round 14
// baseline (speedup 1.0000x reference)
#include <cuda_runtime.h>

// RNN_26895085207932 : Elman RNN, SEQ=2048, B=4096, IN=1, H=32 + Linear(32->1)
// R13: two batch-pairs per warp with a HALF-STEP phase skew (R10 redone):
// iter t = [P.matvec(t) | Q.tail(t-1) | P.tail(t) | Q.matvec(t)] so each
// stream's long-latency tail (shfl 26, MUFU 16) is covered by the other
// stream's independent fma/LDS burst. Weights shared between pairs; one
// LDG.128 feeds both pairs' x; one STG.128 writes both outputs.

typedef unsigned long long ull;

static constexpr int SEQ = 2048;
static constexpr int B   = 4096;
static constexpr int H   = 32;

__device__ __forceinline__ ull pack2(float lo, float hi) {
    ull r; asm("mov.b64 %0, {%1, %2};" : "=l"(r) : "f"(lo), "f"(hi)); return r;
}
__device__ __forceinline__ void unpack2(ull v, float& lo, float& hi) {
    asm("mov.b64 {%0, %1}, %2;" : "=f"(lo), "=f"(hi) : "l"(v));
}
__device__ __forceinline__ ull fma2(ull a, ull b, ull c) {
    ull d; asm("fma.rn.f32x2 %0, %1, %2, %3;" : "=l"(d) : "l"(a), "l"(b), "l"(c)); return d;
}
__device__ __forceinline__ ull add2(ull a, ull b) {
    ull d; asm("add.rn.f32x2 %0, %1, %2;" : "=l"(d) : "l"(a), "l"(b)); return d;
}
__device__ __forceinline__ ull mul2(ull a, ull b) {
    ull d; asm("mul.rn.f32x2 %0, %1, %2;" : "=l"(d) : "l"(a), "l"(b)); return d;
}
__device__ __forceinline__ ull shfl_xor2(ull v, int d) {
    unsigned lo = (unsigned)v, hi = (unsigned)(v >> 32);
    lo = __shfl_xor_sync(0xffffffffu, lo, d);
    hi = __shfl_xor_sync(0xffffffffu, hi, d);
    return ((ull)hi << 32) | (ull)lo;
}
__device__ __forceinline__ float tanh_fast(float z) {
    float r; asm("tanh.approx.f32 %0, %1;" : "=f"(r) : "f"(z)); return r;
}
__device__ __forceinline__ void sts64(ull v, const void* p) {
    asm volatile("st.shared.b64 [%0], %1;"
                 :: "l"(__cvta_generic_to_shared(p)), "l"(v) : "memory");
}
__device__ __forceinline__ float guard_scale(float w) {
    float a = fabsf(w);
    return (a < 1e-6f) ? copysignf(1e-6f, w) : w;
}

// ---- per-stream step halves -------------------------------------------------
// PMAT: load x, seed chain A, run 4-chain matvec from ringP row (T-1).
#define PMAT(T, U, CHK)                                                       \
    {                                                                         \
        xcur = xpipe[U];                                                      \
        if (!(CHK) || ((T) + 4 < SEQ))                                        \
            xpipe[U] = xnext[(size_t)(T) * (B / 4)];                          \
        PpA = fma2(xcur.x, wih2, bias2);                                      \
        PpB = 0; PpC = 0; PpD = 0;                                            \
        const ulonglong2* hp =                                                \
            reinterpret_cast<const ulonglong2*>(&ringP[((T) + 31) & 31][kofs]); \
        _Pragma("unroll")                                                     \
        for (int kk = 0; kk < 4; kk++) {                                      \
            ulonglong2 hv = hp[kk];                                           \
            PpA = fma2(hv.x, wa[2 * kk],     PpA);                            \
            PpB = fma2(hv.x, wb[2 * kk],     PpB);                            \
            PpC = fma2(hv.x, wc[2 * kk],     PpC);                            \
            PpD = fma2(hv.x, wd[2 * kk],     PpD);                            \
            PpA = fma2(hv.y, wa[2 * kk + 1], PpA);                            \
            PpB = fma2(hv.y, wb[2 * kk + 1], PpB);                            \
            PpC = fma2(hv.y, wc[2 * kk + 1], PpC);                            \
            PpD = fma2(hv.y, wd[2 * kk + 1], PpD);                            \
        }                                                                     \
    }

#define PTAIL(T)                                                              \
    {                                                                         \
        ull r1 = shfl_xor2(PpB, 8);                                           \
        ull r2 = shfl_xor2(PpC, 16);                                          \
        ull r3 = shfl_xor2(PpD, 24);                                          \
        ull z  = add2(add2(PpA, r1), add2(r2, r3));                           \
        float zA_, zB_;                                                       \
        unpack2(z, zA_, zB_);                                                 \
        sts64(mul2(pack2(tanh_fast(zA_), tanh_fast(zB_)), sfc2),              \
              &ringP[(T) & 31][myu]);                                         \
    }

#define QMAT(T)                                                               \
    {                                                                         \
        QpA = fma2(xcur.y, wih2, bias2);                                      \
        QpB = 0; QpC = 0; QpD = 0;                                            \
        const ulonglong2* hp =                                                \
            reinterpret_cast<const ulonglong2*>(&ringQ[((T) + 31) & 31][kofs]); \
        _Pragma("unroll")                                                     \
        for (int kk = 0; kk < 4; kk++) {                                      \
            ulonglong2 hv = hp[kk];                                           \
            QpA = fma2(hv.x, wa[2 * kk],     QpA);                            \
            QpB = fma2(hv.x, wb[2 * kk],     QpB);                            \
            QpC = fma2(hv.x, wc[2 * kk],     QpC);                            \
            QpD = fma2(hv.x, wd[2 * kk],     QpD);                            \
            QpA = fma2(hv.y, wa[2 * kk + 1], QpA);                            \
            QpB = fma2(hv.y, wb[2 * kk + 1], QpB);                            \
            QpC = fma2(hv.y, wc[2 * kk + 1], QpC);                            \
            QpD = fma2(hv.y, wd[2 * kk + 1], QpD);                            \
        }                                                                     \
    }

#define QTAIL(T)                                                              \
    {                                                                         \
        ull r1 = shfl_xor2(QpB, 8);                                           \
        ull r2 = shfl_xor2(QpC, 16);                                          \
        ull r3 = shfl_xor2(QpD, 24);                                          \
        ull z  = add2(add2(QpA, r1), add2(r2, r3));                           \
        float zA_, zB_;                                                       \
        unpack2(z, zA_, zB_);                                                 \
        sts64(mul2(pack2(tanh_fast(zA_), tanh_fast(zB_)), sfc2),              \
              &ringQ[(T) & 31][myu]);                                         \
    }

// iter with the skew: Q's tail of step T-1 sits between P's matvec and tail.
#define ITER(T, U, CHK)  PMAT(T, U, CHK) QTAIL((T) - 1) PTAIL(T) QMAT(T)

__global__ void __launch_bounds__(32, 7)
rnn_kernel(const float* __restrict__ x,      // (SEQ, B, 1)
           const float* __restrict__ hidden, // (1, B, H)
           const float* __restrict__ Wih,    // (H, 1)
           const float* __restrict__ bih,    // (H)
           const float* __restrict__ Whh,    // (H, H)
           const float* __restrict__ bhh,    // (H)
           const float* __restrict__ Wfc,    // (1, H)
           const float* __restrict__ bfc,    // (1)
           float* __restrict__ out)          // (SEQ, B, 1)
{
    __shared__ __align__(16) float2 ringP[32][34];  // s*h ring, pair P
    __shared__ __align__(16) float2 ringQ[32][34];  // s*h ring, pair Q

    const int j = threadIdx.x;
    const int q = j >> 3;                // k-quarter this lane reads
    const int g = j & 7;                 // quartet group
    const int myu = 4 * g + q;           // unit this lane owns
    const int ub  = 4 * g + (q ^ 1);
    const int uc  = 4 * g + (q ^ 2);
    const int ud  = 4 * g + (q ^ 3);
    const int kofs = 8 * q;

    const int bx = blockIdx.x;           // batch quad index
    const int b0 = bx * 4;

    // Pre-divided weights (shared by both pairs): w' = Whh / s.
    ull wa[8], wb[8], wc[8], wd[8];
#pragma unroll
    for (int k = 0; k < 8; k++) {
        float inv = 1.0f / guard_scale(Wfc[kofs + k]);
        float a = Whh[myu * H + kofs + k] * inv;
        float b = Whh[ub  * H + kofs + k] * inv;
        float c = Whh[uc  * H + kofs + k] * inv;
        float d = Whh[ud  * H + kofs + k] * inv;
        wa[k] = pack2(a, a);
        wb[k] = pack2(b, b);
        wc[k] = pack2(c, c);
        wd[k] = pack2(d, d);
    }
    const float wih  = Wih[myu];
    const float bias = bih[myu] + bhh[myu];
    const ull wih2   = pack2(wih, wih);
    const ull bias2  = pack2(bias, bias);
    const float sfc  = guard_scale(Wfc[myu]);
    const ull sfc2   = pack2(sfc, sfc);
    const float bfc0 = bfc[0];

    // Initial states in row 31 (step 0 reads row (0+31)&31 = 31).
    ringP[31][myu] = make_float2(sfc * hidden[(size_t)(b0 + 0) * H + myu],
                                 sfc * hidden[(size_t)(b0 + 1) * H + myu]);
    ringQ[31][myu] = make_float2(sfc * hidden[(size_t)(b0 + 2) * H + myu],
                                 sfc * hidden[(size_t)(b0 + 3) * H + myu]);
    __syncwarp();

    // x: one LDG.128 per step feeds both pairs (float2 P | float2 Q).
    const ulonglong2* xg = reinterpret_cast<const ulonglong2*>(x) + bx;
    float4* og           = reinterpret_cast<float4*>(out) + bx;

    ulonglong2 xpipe[4];
#pragma unroll
    for (int i = 0; i < 4; i++) xpipe[i] = xg[(size_t)i * (B / 4)];
    const ulonglong2* xnext = xg + 4 * (size_t)(B / 4);

    ull PpA, PpB, PpC, PpD, QpA, QpB, QpC, QpD;
    ulonglong2 xcur;

    for (int base = 0; base < SEQ; base += 32) {
        if (base + 32 < SEQ) {
            // First iter of the block: QTAIL(base-1) already done in the
            // previous block's epilogue (or init) — skip it.
            PMAT(base, 0, false) PTAIL(base) QMAT(base)
            ITER(base + 1, 1, false)
            ITER(base + 2, 2, false)
            ITER(base + 3, 3, false)
#pragma unroll 1
            for (int qq = 1; qq < 8; qq++) {
                const int s4 = base + 4 * qq;
                ITER(s4 + 0, 0, false)
                ITER(s4 + 1, 1, false)
                ITER(s4 + 2, 2, false)
                ITER(s4 + 3, 3, false)
            }
            QTAIL(base + 31)   // epilogue: finish Q's last row before reduction
        } else {
            PMAT(base, 0, true) PTAIL(base) QMAT(base)
            ITER(base + 1, 1, true)
            ITER(base + 2, 2, true)
            ITER(base + 3, 3, true)
#pragma unroll 1
            for (int qq = 1; qq < 8; qq++) {
                const int s4 = base + 4 * qq;
                ITER(s4 + 0, 0, true)
                ITER(s4 + 1, 1, true)
                ITER(s4 + 2, 2, true)
                ITER(s4 + 3, 3, true)
            }
            QTAIL(base + 31)
        }

        // Output reduction: lane j sums ring rows j (= timestep base+j) of
        // both pairs; one STG.128 writes all 4 batches.
        {
            const ulonglong2* prP = reinterpret_cast<const ulonglong2*>(&ringP[j][0]);
            const ulonglong2* prQ = reinterpret_cast<const ulonglong2*>(&ringQ[j][0]);
            ull p0 = 0, p1 = 0, p2 = 0, p3 = 0;
            ull q0 = 0, q1 = 0, q2 = 0, q3 = 0;
#pragma unroll
            for (int g2 = 0; g2 < 8; g2++) {
                ulonglong2 a = prP[2 * g2];
                ulonglong2 b = prP[2 * g2 + 1];
                p0 = add2(p0, a.x); p1 = add2(p1, a.y);
                p2 = add2(p2, b.x); p3 = add2(p3, b.y);
                ulonglong2 c = prQ[2 * g2];
                ulonglong2 d = prQ[2 * g2 + 1];
                q0 = add2(q0, c.x); q1 = add2(q1, c.y);
                q2 = add2(q2, d.x); q3 = add2(q3, d.y);
            }
            ull svP = add2(add2(p0, p1), add2(p2, p3));
            ull svQ = add2(add2(q0, q1), add2(q2, q3));
            float oA, oB, oC, oD;
            unpack2(svP, oA, oB);
            unpack2(svQ, oC, oD);
            og[(size_t)(base + j) * (B / 4)] =
                make_float4(oA + bfc0, oB + bfc0, oC + bfc0, oD + bfc0);
        }
    }
}

extern "C" void kernel_launch(void* const* d_in, const int* in_sizes, int n_in,
                              void* d_out, int out_size) {
    const float* x      = (const float*)d_in[0];
    const float* hidden = (const float*)d_in[1];
    const float* Wih    = (const float*)d_in[2];
    const float* bih    = (const float*)d_in[3];
    const float* Whh    = (const float*)d_in[4];
    const float* bhh    = (const float*)d_in[5];
    const float* Wfc    = (const float*)d_in[6];
    const float* bfc    = (const float*)d_in[7];
    (void)in_sizes; (void)n_in; (void)out_size;

    rnn_kernel<<<B / 4, 32>>>(x, hidden, Wih, bih, Whh, bhh, Wfc, bfc, (float*)d_out);
}